// round 3
// baseline (speedup 1.0000x reference)
#include <cuda_runtime.h>
#include <cstddef>

// IntegerNeuron: T-step integrate-and-fire scan over [T,B,C,H,W] fp32.
// Pure HBM streaming (537 MB compulsory). R3: persistent single-wave grid
// (148 SMs x 8 CTAs, grid-stride loop) to eliminate ~7 wave transitions
// and tail-wave underutilization; sustained MLP=8 per loop iteration.

#define T_STEPS 8
#define B_DIM   32
#define C_DIM   256
#define H_DIM   32
#define W_DIM   32
#define EPS_F   1e-12f

#define N4 (B_DIM * C_DIM * H_DIM * W_DIM / 4)   // 2,097,152 float4 columns per T-slice

#define NUM_SMS     148
#define CTAS_PER_SM 8
#define THREADS     256
#define GRID        (NUM_SMS * CTAS_PER_SM)       // 1184 CTAs = exactly one wave

__global__ __launch_bounds__(THREADS, CTAS_PER_SM) void integer_neuron_kernel(
    const float4* __restrict__ x4,         // [T, N4]
    const float*  __restrict__ prev_scale, // [C]
    const float*  __restrict__ prev_bias,  // [C]
    const float*  __restrict__ vth,        // [C]
    const float*  __restrict__ tau_ptr,    // [1]
    const int*    __restrict__ is_first,   // [1]
    float4*       __restrict__ o4)         // [T, N4]
{
    const int stride = GRID * THREADS;                       // 303,104
    const float tau = __ldg(tau_ptr);
    const float drive_mul = (__ldg(is_first) != 0) ? 1.0f : tau;

    for (int idx = blockIdx.x * THREADS + threadIdx.x; idx < N4; idx += stride) {
        // channel of this float4 column: element = idx*4, H*W = 1024, C = 256
        const int c = ((idx << 2) >> 10) & (C_DIM - 1);
        const float inv = tau / (__ldg(prev_scale + c) + EPS_F);
        const float bias_scaled = nearbyintf(__ldg(prev_bias + c) * inv); // half-to-even
        const float vth_scaled  = nearbyintf(__ldg(vth + c) * inv);

        // all 8 T-slice loads up front: MLP=8, independent addresses
        float4 xs[T_STEPS];
#pragma unroll
        for (int t = 0; t < T_STEPS; t++)
            xs[t] = __ldcs(x4 + (size_t)t * N4 + idx);

        float4 mem = make_float4(0.f, 0.f, 0.f, 0.f);
#pragma unroll
        for (int t = 0; t < T_STEPS; t++) {
            const float4 xt = xs[t];
            // reference eval order: mem = (mem + x*tau) + bias_scaled
            mem.x = (mem.x + xt.x * drive_mul) + bias_scaled;
            mem.y = (mem.y + xt.y * drive_mul) + bias_scaled;
            mem.z = (mem.z + xt.z * drive_mul) + bias_scaled;
            mem.w = (mem.w + xt.w * drive_mul) + bias_scaled;

            float4 sp;
            sp.x = (mem.x >= vth_scaled) ? 1.0f : 0.0f;
            sp.y = (mem.y >= vth_scaled) ? 1.0f : 0.0f;
            sp.z = (mem.z >= vth_scaled) ? 1.0f : 0.0f;
            sp.w = (mem.w >= vth_scaled) ? 1.0f : 0.0f;

            mem.x -= sp.x * vth_scaled;
            mem.y -= sp.y * vth_scaled;
            mem.z -= sp.z * vth_scaled;
            mem.w -= sp.w * vth_scaled;

            __stcs(o4 + (size_t)t * N4 + idx, sp);
        }
    }
}

extern "C" void kernel_launch(void* const* d_in, const int* in_sizes, int n_in,
                              void* d_out, int out_size)
{
    const float4* x_accum    = (const float4*)d_in[0];
    const float*  prev_scale = (const float*)d_in[1];
    const float*  prev_bias  = (const float*)d_in[2];
    const float*  vth        = (const float*)d_in[3];
    const float*  tau        = (const float*)d_in[4];
    const int*    is_first   = (const int*)d_in[5];
    float4* out = (float4*)d_out;

    integer_neuron_kernel<<<GRID, THREADS>>>(
        x_accum, prev_scale, prev_bias, vth, tau, is_first, out);
}

// round 5
// speedup vs baseline: 1.3374x; 1.3374x over previous
#include <cuda_runtime.h>
#include <cstddef>

// IntegerNeuron: T-step integrate-and-fire scan over [T,B,C,H,W] fp32.
// Pure HBM streaming (512 MiB compulsory, 1:1 R:W mix). R4 (retry after
// infra failure): flat launch (persistent grid regressed — it serialized
// MLP), two float4 columns per thread with all 16 LDG.128 front-loaded
// (256 B in flight per thread).

#define T_STEPS 8
#define B_DIM   32
#define C_DIM   256
#define H_DIM   32
#define W_DIM   32
#define EPS_F   1e-12f

#define N4   (B_DIM * C_DIM * H_DIM * W_DIM / 4)  // 2,097,152 float4 cols per T-slice
#define HALF (N4 / 2)                              // 1,048,576

__global__ __launch_bounds__(256) void integer_neuron_kernel(
    const float4* __restrict__ x4,         // [T, N4]
    const float*  __restrict__ prev_scale, // [C]
    const float*  __restrict__ prev_bias,  // [C]
    const float*  __restrict__ vth,        // [C]
    const float*  __restrict__ tau_ptr,    // [1]
    const int*    __restrict__ is_first,   // [1]
    float4*       __restrict__ o4)         // [T, N4]
{
    const int idxA = blockIdx.x * blockDim.x + threadIdx.x;  // col A: [0, HALF)
    const int idxB = idxA + HALF;                            // col B: [HALF, N4)

    const float tau = __ldg(tau_ptr);
    const float drive_mul = (__ldg(is_first) != 0) ? 1.0f : tau;

    // per-channel params for each column (element = idx*4, H*W=1024, C=256)
    const int cA = ((idxA << 2) >> 10) & (C_DIM - 1);
    const int cB = ((idxB << 2) >> 10) & (C_DIM - 1);
    const float invA = tau / (__ldg(prev_scale + cA) + EPS_F);
    const float invB = tau / (__ldg(prev_scale + cB) + EPS_F);
    const float biasA = nearbyintf(__ldg(prev_bias + cA) * invA); // half-to-even = jnp.round
    const float biasB = nearbyintf(__ldg(prev_bias + cB) * invB);
    const float vthA  = nearbyintf(__ldg(vth + cA) * invA);
    const float vthB  = nearbyintf(__ldg(vth + cB) * invB);

    // Front-load ALL 16 independent LDG.128s (MLP=16 per thread).
    float4 xa[T_STEPS], xb[T_STEPS];
#pragma unroll
    for (int t = 0; t < T_STEPS; t++) {
        xa[t] = __ldcs(x4 + (size_t)t * N4 + idxA);
        xb[t] = __ldcs(x4 + (size_t)t * N4 + idxB);
    }

    float4 memA = make_float4(0.f, 0.f, 0.f, 0.f);
    float4 memB = make_float4(0.f, 0.f, 0.f, 0.f);

#pragma unroll
    for (int t = 0; t < T_STEPS; t++) {
        // ---- column A ----  (reference order: mem = (mem + x*tau) + bias)
        {
            const float4 xt = xa[t];
            memA.x = (memA.x + xt.x * drive_mul) + biasA;
            memA.y = (memA.y + xt.y * drive_mul) + biasA;
            memA.z = (memA.z + xt.z * drive_mul) + biasA;
            memA.w = (memA.w + xt.w * drive_mul) + biasA;
            float4 sp;
            sp.x = (memA.x >= vthA) ? 1.0f : 0.0f;
            sp.y = (memA.y >= vthA) ? 1.0f : 0.0f;
            sp.z = (memA.z >= vthA) ? 1.0f : 0.0f;
            sp.w = (memA.w >= vthA) ? 1.0f : 0.0f;
            memA.x -= sp.x * vthA;
            memA.y -= sp.y * vthA;
            memA.z -= sp.z * vthA;
            memA.w -= sp.w * vthA;
            __stcs(o4 + (size_t)t * N4 + idxA, sp);
        }
        // ---- column B ----
        {
            const float4 xt = xb[t];
            memB.x = (memB.x + xt.x * drive_mul) + biasB;
            memB.y = (memB.y + xt.y * drive_mul) + biasB;
            memB.z = (memB.z + xt.z * drive_mul) + biasB;
            memB.w = (memB.w + xt.w * drive_mul) + biasB;
            float4 sp;
            sp.x = (memB.x >= vthB) ? 1.0f : 0.0f;
            sp.y = (memB.y >= vthB) ? 1.0f : 0.0f;
            sp.z = (memB.z >= vthB) ? 1.0f : 0.0f;
            sp.w = (memB.w >= vthB) ? 1.0f : 0.0f;
            memB.x -= sp.x * vthB;
            memB.y -= sp.y * vthB;
            memB.z -= sp.z * vthB;
            memB.w -= sp.w * vthB;
            __stcs(o4 + (size_t)t * N4 + idxB, sp);
        }
    }
}

extern "C" void kernel_launch(void* const* d_in, const int* in_sizes, int n_in,
                              void* d_out, int out_size)
{
    const float4* x_accum    = (const float4*)d_in[0];
    const float*  prev_scale = (const float*)d_in[1];
    const float*  prev_bias  = (const float*)d_in[2];
    const float*  vth        = (const float*)d_in[3];
    const float*  tau        = (const float*)d_in[4];
    const int*    is_first   = (const int*)d_in[5];
    float4* out = (float4*)d_out;

    const int threads = 256;
    const int blocks  = HALF / threads;  // 4096, exact
    integer_neuron_kernel<<<blocks, threads>>>(
        x_accum, prev_scale, prev_bias, vth, tau, is_first, out);
}

// round 6
// speedup vs baseline: 1.3424x; 1.0037x over previous
#include <cuda_runtime.h>
#include <cstddef>

// IntegerNeuron: T-step integrate-and-fire scan over [T,B,C,H,W] fp32.
// Pure HBM streaming, compulsory 512 MiB, 1:1 R:W mix — measured ceiling
// ~6.2 TB/s. Final shape: flat grid (8192x256), one float4 column per
// thread, all 8 T-slice loads front-batched (MLP=8), loads L2-only
// (__ldcg, L1 is useless for touch-once), streaming stores (__stcs).
// [Persistent grid regressed (serialized MLP); MLP=16/thread was neutral
//  (occupancy tradeoff); L2 hints alone were neutral.]

#define T_STEPS 8
#define B_DIM   32
#define C_DIM   256
#define H_DIM   32
#define W_DIM   32
#define EPS_F   1e-12f

#define N4 (B_DIM * C_DIM * H_DIM * W_DIM / 4)   // 2,097,152 float4 cols per T-slice

__global__ __launch_bounds__(256) void integer_neuron_kernel(
    const float4* __restrict__ x4,         // [T, N4]
    const float*  __restrict__ prev_scale, // [C]
    const float*  __restrict__ prev_bias,  // [C]
    const float*  __restrict__ vth,        // [C]
    const float*  __restrict__ tau_ptr,    // [1]
    const int*    __restrict__ is_first,   // [1]
    float4*       __restrict__ o4)         // [T, N4]
{
    const int idx = blockIdx.x * blockDim.x + threadIdx.x;  // exact grid, no tail

    // channel of this float4 column: element = idx*4, H*W = 1024, C = 256
    const int c = ((idx << 2) >> 10) & (C_DIM - 1);

    const float tau = __ldg(tau_ptr);
    const float inv = tau / (__ldg(prev_scale + c) + EPS_F);
    const float bias_scaled = nearbyintf(__ldg(prev_bias + c) * inv); // half-to-even = jnp.round
    const float vth_scaled  = nearbyintf(__ldg(vth + c) * inv);
    const float drive_mul   = (__ldg(is_first) != 0) ? 1.0f : tau;

    // Front-batch all 8 independent T-slice loads (MLP=8), L2-only.
    float4 xs[T_STEPS];
#pragma unroll
    for (int t = 0; t < T_STEPS; t++)
        xs[t] = __ldcg(x4 + (size_t)t * N4 + idx);

    float4 mem = make_float4(0.f, 0.f, 0.f, 0.f);

#pragma unroll
    for (int t = 0; t < T_STEPS; t++) {
        const float4 xt = xs[t];
        // reference eval order: mem = (mem + x*tau) + bias_scaled
        mem.x = (mem.x + xt.x * drive_mul) + bias_scaled;
        mem.y = (mem.y + xt.y * drive_mul) + bias_scaled;
        mem.z = (mem.z + xt.z * drive_mul) + bias_scaled;
        mem.w = (mem.w + xt.w * drive_mul) + bias_scaled;

        float4 sp;
        sp.x = (mem.x >= vth_scaled) ? 1.0f : 0.0f;
        sp.y = (mem.y >= vth_scaled) ? 1.0f : 0.0f;
        sp.z = (mem.z >= vth_scaled) ? 1.0f : 0.0f;
        sp.w = (mem.w >= vth_scaled) ? 1.0f : 0.0f;

        mem.x -= sp.x * vth_scaled;
        mem.y -= sp.y * vth_scaled;
        mem.z -= sp.z * vth_scaled;
        mem.w -= sp.w * vth_scaled;

        __stcs(o4 + (size_t)t * N4 + idx, sp);
    }
}

extern "C" void kernel_launch(void* const* d_in, const int* in_sizes, int n_in,
                              void* d_out, int out_size)
{
    const float4* x_accum    = (const float4*)d_in[0];
    const float*  prev_scale = (const float*)d_in[1];
    const float*  prev_bias  = (const float*)d_in[2];
    const float*  vth        = (const float*)d_in[3];
    const float*  tau        = (const float*)d_in[4];
    const int*    is_first   = (const int*)d_in[5];
    float4* out = (float4*)d_out;

    const int threads = 256;
    const int blocks  = N4 / threads;  // 8192, exact
    integer_neuron_kernel<<<blocks, threads>>>(
        x_accum, prev_scale, prev_bias, vth, tau, is_first, out);
}